// round 2
// baseline (speedup 1.0000x reference)
#include <cuda_runtime.h>
#include <stdint.h>

#define NUM_USERS 100000
#define NUM_ITEMS 50000
#define N_NODES   150000
#define D         64
#define D4        16          // D / 4 float4 per row
#define E_EDGES   1200000
#define N_LAYERS  3

// Scratch (allocation-free: __device__ globals)
__device__ float g_x0[N_NODES * D];     // ping
__device__ float g_x1[N_NODES * D];     // pong
__device__ float g_deg[2 * N_NODES];    // [0:N) deg_row, [N:2N) deg_col -> transformed to inv-sqrt in place
__device__ float g_norm[E_EDGES];

// ---------------- utility kernels ----------------

__global__ void k_zero4(float4* p, int n4) {
    int i = blockIdx.x * blockDim.x + threadIdx.x;
    if (i < n4) p[i] = make_float4(0.f, 0.f, 0.f, 0.f);
}

__global__ void k_copy4(float4* dst, const float4* src, int n4) {
    int i = blockIdx.x * blockDim.x + threadIdx.x;
    if (i < n4) dst[i] = src[i];
}

// degree counting: one thread per edge, two scalar atomics
__global__ void k_deg(const int* __restrict__ row, const int* __restrict__ col,
                      float* __restrict__ deg) {
    int e = blockIdx.x * blockDim.x + threadIdx.x;
    if (e < E_EDGES) {
        atomicAdd(&deg[row[e]], 1.0f);
        atomicAdd(&deg[N_NODES + col[e]], 1.0f);
    }
}

// in-place deg -> deg>0 ? rsqrt(deg) : 0
__global__ void k_inv(float* __restrict__ deg, int n) {
    int i = blockIdx.x * blockDim.x + threadIdx.x;
    if (i < n) {
        float d = deg[i];
        deg[i] = (d > 0.f) ? rsqrtf(d) : 0.f;
    }
}

// norm[e] = inv_row[row[e]] * inv_col[col[e]]
__global__ void k_norm(const int* __restrict__ row, const int* __restrict__ col,
                       const float* __restrict__ inv, float* __restrict__ norm) {
    int e = blockIdx.x * blockDim.x + threadIdx.x;
    if (e < E_EDGES) {
        norm[e] = inv[row[e]] * inv[N_NODES + col[e]];
    }
}

// ---------------- the SpMM layer ----------------
// 16 threads per edge; thread q handles float4 #q of the 64-dim row.
// Gather src[row[e]] (coalesced 256B), scale by norm[e], vector-red into dst[col[e]].
__global__ void k_scatter(const int* __restrict__ row, const int* __restrict__ col,
                          const float* __restrict__ norm,
                          const float4* __restrict__ src, float4* __restrict__ dst) {
    int t = blockIdx.x * blockDim.x + threadIdx.x;
    int e = t >> 4;
    int q = t & 15;
    if (e >= E_EDGES) return;

    int   r = __ldg(&row[e]);
    int   c = __ldg(&col[e]);
    float w = __ldg(&norm[e]);

    float4 v = __ldg(&src[(size_t)r * D4 + q]);
    v.x *= w; v.y *= w; v.z *= w; v.w *= w;

    float4* addr = &dst[(size_t)c * D4 + q];
    asm volatile("red.global.add.v4.f32 [%0], {%1,%2,%3,%4};"
                 :: "l"(addr), "f"(v.x), "f"(v.y), "f"(v.z), "f"(v.w)
                 : "memory");
}

// out += x
__global__ void k_add4(float4* __restrict__ out, const float4* __restrict__ x, int n4) {
    int i = blockIdx.x * blockDim.x + threadIdx.x;
    if (i < n4) {
        float4 a = out[i];
        float4 b = x[i];
        a.x += b.x; a.y += b.y; a.z += b.z; a.w += b.w;
        out[i] = a;
    }
}

// out = (out + x) * s   (fused last-layer accumulate + final scale)
__global__ void k_add_scale4(float4* __restrict__ out, const float4* __restrict__ x,
                             float s, int n4) {
    int i = blockIdx.x * blockDim.x + threadIdx.x;
    if (i < n4) {
        float4 a = out[i];
        float4 b = x[i];
        a.x = (a.x + b.x) * s;
        a.y = (a.y + b.y) * s;
        a.z = (a.z + b.z) * s;
        a.w = (a.w + b.w) * s;
        out[i] = a;
    }
}

// ---------------- launch ----------------

extern "C" void kernel_launch(void* const* d_in, const int* in_sizes, int n_in,
                              void* d_out, int out_size) {
    const int*   edge = (const int*)d_in[0];       // [2, E]
    const float* emb  = (const float*)d_in[1];     // [N, 64]
    float*       out  = (float*)d_out;             // [N, 64]

    const int* row = edge;
    const int* col = edge + E_EDGES;

    float4* x0p;  cudaGetSymbolAddress((void**)&x0p, g_x0);
    float4* x1p;  cudaGetSymbolAddress((void**)&x1p, g_x1);
    float*  degp; cudaGetSymbolAddress((void**)&degp, g_deg);
    float*  nrmp; cudaGetSymbolAddress((void**)&nrmp, g_norm);

    const int TB = 256;
    const int n4_x   = N_NODES * D4;                 // float4 count of one x buffer
    const int gx4    = (n4_x + TB - 1) / TB;
    const int gE     = (E_EDGES + TB - 1) / TB;
    const int gE16   = (E_EDGES * 16 + TB - 1) / TB;
    const int gDeg   = (2 * N_NODES + TB - 1) / TB;
    const int gDeg4  = (2 * N_NODES / 4 + TB - 1) / TB;

    // 1) degrees -> inv-sqrt -> edge norms
    k_zero4<<<gDeg4, TB>>>((float4*)degp, 2 * N_NODES / 4);
    k_deg<<<gE, TB>>>(row, col, degp);
    k_inv<<<gDeg, TB>>>(degp, 2 * N_NODES);
    k_norm<<<gE, TB>>>(row, col, degp, nrmp);

    // 2) out = embedding (layer-0 term of the accumulator)
    k_copy4<<<gx4, TB>>>((float4*)out, (const float4*)emb, n4_x);

    // 3) three propagation layers
    const float4* src = (const float4*)emb;
    float4* bufs[2] = { x0p, x1p };
    for (int l = 0; l < N_LAYERS; ++l) {
        float4* dst = bufs[l & 1];
        k_zero4<<<gx4, TB>>>(dst, n4_x);
        k_scatter<<<gE16, TB>>>(row, col, nrmp, src, dst);
        if (l < N_LAYERS - 1) {
            k_add4<<<gx4, TB>>>((float4*)out, dst, n4_x);
        } else {
            k_add_scale4<<<gx4, TB>>>((float4*)out, dst,
                                      1.0f / (N_LAYERS + 1), n4_x);
        }
        src = dst;
    }
}

// round 3
// speedup vs baseline: 1.5346x; 1.5346x over previous
#include <cuda_runtime.h>
#include <stdint.h>

#define NUM_USERS 100000
#define N_NODES   150000
#define D         64
#define D4        16
#define E_EDGES   1200000
#define N_LAYERS  3

// ---------------- device scratch (allocation-free) ----------------
__device__ float g_x0[N_NODES * D];        // ping
__device__ float g_x1[N_NODES * D];        // pong
__device__ int   g_degi[2 * N_NODES];      // [0,N): deg_row  [N,2N): deg_col
__device__ float g_inv [2 * N_NODES];      // rsqrt(deg) or 0
__device__ int   g_offs[N_NODES];          // CSR start per dst node (disjoint ranges)
__device__ int   g_cursor[N_NODES];        // fill cursors (copy of offs)
__device__ int2  g_csr[E_EDGES];           // packed {src_row, norm_as_bits}
__device__ int   g_total;                  // range allocator

// ---------------- setup kernels ----------------

__global__ void k_zero_meta() {
    int i = blockIdx.x * blockDim.x + threadIdx.x;
    if (i < 2 * N_NODES) g_degi[i] = 0;
    if (i == 0) g_total = 0;
}

__global__ void k_deg(const int* __restrict__ row, const int* __restrict__ col) {
    int e = blockIdx.x * blockDim.x + threadIdx.x;
    if (e < E_EDGES) {
        atomicAdd(&g_degi[row[e]], 1);
        atomicAdd(&g_degi[N_NODES + col[e]], 1);
    }
}

__global__ void k_inv() {
    int i = blockIdx.x * blockDim.x + threadIdx.x;
    if (i < 2 * N_NODES) {
        int d = g_degi[i];
        g_inv[i] = (d > 0) ? rsqrtf((float)d) : 0.0f;
    }
}

// Allocate disjoint CSR ranges per dst node. Order across warps is irrelevant —
// only disjointness matters — so a warp-aggregated atomic replaces a full scan.
__global__ void k_alloc() {
    int n    = blockIdx.x * blockDim.x + threadIdx.x;
    int lane = threadIdx.x & 31;
    int d    = (n < N_NODES) ? g_degi[N_NODES + n] : 0;

    int x = d;                               // warp inclusive scan
    #pragma unroll
    for (int o = 1; o < 32; o <<= 1) {
        int y = __shfl_up_sync(0xffffffffu, x, o);
        if (lane >= o) x += y;
    }
    int wtot = __shfl_sync(0xffffffffu, x, 31);
    int base = 0;
    if (lane == 0) base = atomicAdd(&g_total, wtot);
    base = __shfl_sync(0xffffffffu, base, 0);

    if (n < N_NODES) {
        int excl = base + x - d;
        g_offs[n]   = excl;
        g_cursor[n] = excl;
    }
}

// Scatter edges into CSR slots; fold symmetric norm into the record.
__global__ void k_fill(const int* __restrict__ row, const int* __restrict__ col) {
    int e = blockIdx.x * blockDim.x + threadIdx.x;
    if (e < E_EDGES) {
        int r = row[e], c = col[e];
        int slot = atomicAdd(&g_cursor[c], 1);
        float w = g_inv[r] * g_inv[N_NODES + c];
        g_csr[slot] = make_int2(r, __float_as_int(w));
    }
}

// ---------------- propagation layer: pull gather-reduce ----------------
// 16 threads (half-warp) per dst node; lane q owns float4 #q of the 64-dim row.
// MODE 0: out = src[n] + acc; dst = acc         (src == embedding, fuses copy)
// MODE 1: out += acc;         dst = acc
// MODE 2: out = (out + acc) * 0.25f             (no scratch write needed)
template<int MODE>
__global__ void k_layer(const float4* __restrict__ src,
                        float4* __restrict__ dst,
                        float4* __restrict__ out) {
    int t = blockIdx.x * blockDim.x + threadIdx.x;
    int n = t >> 4;
    int q = t & 15;
    if (n >= N_NODES) return;

    int beg  = __ldg(&g_offs[n]);
    int dcnt = __ldg(&g_degi[N_NODES + n]);

    float4 acc = make_float4(0.f, 0.f, 0.f, 0.f);
    int2 e;
    if (dcnt > 0) e = __ldg(&g_csr[beg]);     // software prefetch pipeline
    for (int j = 0; j < dcnt; ++j) {
        int   r = e.x;
        float w = __int_as_float(e.y);
        if (j + 1 < dcnt) e = __ldg(&g_csr[beg + j + 1]);
        float4 v = __ldg(&src[(size_t)r * D4 + q]);
        acc.x = fmaf(w, v.x, acc.x);
        acc.y = fmaf(w, v.y, acc.y);
        acc.z = fmaf(w, v.z, acc.z);
        acc.w = fmaf(w, v.w, acc.w);
    }

    size_t oi = (size_t)n * D4 + q;
    if (MODE == 0) {
        float4 s = __ldg(&src[oi]);
        out[oi] = make_float4(s.x + acc.x, s.y + acc.y, s.z + acc.z, s.w + acc.w);
        dst[oi] = acc;
    } else if (MODE == 1) {
        float4 o = out[oi];
        out[oi] = make_float4(o.x + acc.x, o.y + acc.y, o.z + acc.z, o.w + acc.w);
        dst[oi] = acc;
    } else {
        float4 o = out[oi];
        const float s = 0.25f;
        out[oi] = make_float4((o.x + acc.x) * s, (o.y + acc.y) * s,
                              (o.z + acc.z) * s, (o.w + acc.w) * s);
    }
}

// ---------------- launch ----------------

extern "C" void kernel_launch(void* const* d_in, const int* in_sizes, int n_in,
                              void* d_out, int out_size) {
    const int*   edge = (const int*)d_in[0];   // [2, E]
    const float* emb  = (const float*)d_in[1]; // [N, 64]
    float*       out  = (float*)d_out;

    const int* row = edge;
    const int* col = edge + E_EDGES;

    float4* x0p; cudaGetSymbolAddress((void**)&x0p, g_x0);
    float4* x1p; cudaGetSymbolAddress((void**)&x1p, g_x1);

    const int TB = 256;
    const int gE    = (E_EDGES + TB - 1) / TB;
    const int gMeta = (2 * N_NODES + TB - 1) / TB;
    const int gN    = (N_NODES + TB - 1) / TB;
    const int gLyr  = (N_NODES * 16 + TB - 1) / TB;

    // CSR build
    k_zero_meta<<<gMeta, TB>>>();
    k_deg<<<gE, TB>>>(row, col);
    k_inv<<<gMeta, TB>>>();
    k_alloc<<<gN, TB>>>();
    k_fill<<<gE, TB>>>(row, col);

    // 3 propagation layers, accumulate + final scale fused into epilogues
    k_layer<0><<<gLyr, TB>>>((const float4*)emb, x0p, (float4*)out);
    k_layer<1><<<gLyr, TB>>>((const float4*)x0p, x1p, (float4*)out);
    k_layer<2><<<gLyr, TB>>>((const float4*)x1p, nullptr, (float4*)out);
}